// round 16
// baseline (speedup 1.0000x reference)
#include <cuda_runtime.h>
#include <cstdint>

typedef unsigned long long ULL;

// ---------------- device scratch (no allocations allowed) ----------------
// Packed, zero-padded weights: Wpad[lp][c] = (Win_real[c][lp-9], Win_imag[c][lp-9]),
// zero outside l in [0, 4086]. lp in [0, 4105).
__device__ __align__(16) float2 wpad_g[4105 * 16];
// Stage-1 partial sums: [b][s][idx]  (b:256, s:16, idx:320 = (c*10+w)*2+comp)
__device__ float fpart_g[256 * 16 * 320];
// Pre-batchnorm output: [b][c*2+o]
__device__ float out_g[256 * 32];

// ---------------- packed f32x2 FMA (FFMA2) ----------------
__device__ __forceinline__ ULL fma2(ULL a, ULL b, ULL c) {
    ULL d;
    asm("fma.rn.f32x2 %0, %1, %2, %3;" : "=l"(d) : "l"(a), "l"(b), "l"(c));
    return d;
}
__device__ __forceinline__ float2 u2f2(ULL v) {
    return make_float2(__uint_as_float((unsigned)(v & 0xffffffffULL)),
                       __uint_as_float((unsigned)(v >> 32)));
}
__device__ __forceinline__ void cp16(uint32_t saddr, const void* gaddr) {
    asm volatile("cp.async.cg.shared.global [%0], [%1], 16;" :: "r"(saddr), "l"(gaddr));
}

// ---------------- kernel 0: pack + pad weights (coalesced reads) ----------------
// grid (16 channels, 17 lp-chunks), 256 threads; lanes read consecutive l.
__global__ void __launch_bounds__(256) pack_kernel(const float* __restrict__ wr,
                                                   const float* __restrict__ wi) {
    int c  = blockIdx.x;
    int lp = blockIdx.y * 256 + threadIdx.x;
    if (lp >= 4105) return;
    int l = lp - 9;
    float2 v = make_float2(0.f, 0.f);
    if (l >= 0 && l < 4087) {
        v.x = wr[c * 4087 + l];   // coalesced: lanes -> consecutive l
        v.y = wi[c * 4087 + l];
    }
    wpad_g[lp * 16 + c] = v;      // scattered 8B stores (fire-and-forget)
}

// ---------------- kernel 1: depthwise sliding filters (stage 1) ----------------
// grid (256 batches, 16 segments), 256 threads = 16 channels x 16 j-chunks.
// The block cp.async's its full 32KB x-tile (256 pos x 16 ch) into smem in one
// 8-deep burst per thread, then computes 16 positions/thread from smem with a
// 10-deep rotating register weight window LDG'd from L2-hot wpad_g.
// f[b,w,c] = sum_p x[b,p,c] * Wpad[p + 9 - w]
__global__ void __launch_bounds__(256) stage1_kernel(const float* __restrict__ x) {
    __shared__ __align__(16) ULL tile[256 * 16];   // 32KB: tile[pl*16 + c]
    __shared__ float red[8][320];                  // 10.2KB per-warp partials

    int b    = blockIdx.x;
    int s    = blockIdx.y;             // 0..15
    int tid  = threadIdx.x;
    int c    = tid & 15;
    int j    = tid >> 4;               // 0..15
    int pl0  = j * 16;                 // local position start
    int ps0  = s * 256;                // segment start
    int warp = tid >> 5;               // 0..7

    // ---- cooperative x-tile fill: 32KB = 2048 float4, 8 per thread ----
    {
        const char* gsrc = (const char*)((const ULL*)x + ((size_t)b * 4096 + ps0) * 16);
        uint32_t sdst = (uint32_t)__cvta_generic_to_shared(tile);
#pragma unroll
        for (int k = 0; k < 8; k++)
            cp16(sdst + (tid + k * 256) * 16, gsrc + (size_t)(tid + k * 256) * 16);
        asm volatile("cp.async.commit_group;");
    }

    // weight pointer for this thread's window (overlaps the fill)
    const ULL* wp = (const ULL*)wpad_g + (size_t)(ps0 + pl0) * 16 + c;   // wp[k*16]=Wpad[ps0+pl0+k]
    ULL wbuf[10];
#pragma unroll
    for (int k = 0; k < 9; k++) wbuf[k] = wp[(size_t)k * 16];

    ULL acc[10];
#pragma unroll
    for (int w = 0; w < 10; w++) acc[w] = 0ULL;

    asm volatile("cp.async.wait_group 0;" ::: "memory");
    __syncthreads();

    // ---- mainloop: x from smem (no DRAM latency), weights from L2 ----
#pragma unroll
    for (int t = 0; t < 16; t++) {
        ULL xv = tile[(pl0 + t) * 16 + c];
        wbuf[(t + 9) % 10] = wp[(size_t)(t + 9) * 16];   // Wpad[p0+t+9]
#pragma unroll
        for (int w = 0; w < 10; w++)
            acc[w] = fma2(xv, wbuf[(t + 9 - w) % 10], acc[w]);   // Wpad[p+9-w]
    }

    // ---- epilogue: shfl j-pair combine + 8-row conflict-free reduce ----
#pragma unroll
    for (int w = 0; w < 10; w++) {
        float2 f = u2f2(acc[w]);
        f.x += __shfl_xor_sync(0xffffffffu, f.x, 16);
        f.y += __shfl_xor_sync(0xffffffffu, f.y, 16);
        if ((tid & 16) == 0) {
            red[warp][(c * 10 + w) * 2 + 0] = f.x;
            red[warp][(c * 10 + w) * 2 + 1] = f.y;
        }
    }
    __syncthreads();

    for (int idx = tid; idx < 320; idx += 256) {
        float v = 0.f;
#pragma unroll
        for (int ww = 0; ww < 8; ww++) v += red[ww][idx];
        fpart_g[((size_t)b * 16 + s) * 320 + idx] = v;
    }
}

// ---------------- kernel 2: amp + Linear(2C->2) + out filter ----------------
// one block per b, 320 threads; coalesced s-reduction from L2-hot fpart.
__global__ void __launch_bounds__(320) stage23_kernel(const float* __restrict__ Wnl,
                                                      const float* __restrict__ WoR,
                                                      const float* __restrict__ WoI) {
    __shared__ float tf[10][32];       // [w][i], i<16: amp*fr, i>=16: amp*fi
    __shared__ float contrib[10][32];  // [w][c*2+o]

    int b = blockIdx.x;
    int tid = threadIdx.x;

    // reduce over s=16 directly from L2; idx = (c*10+w)*2+o = tid (coalesced)
    {
        const float* fp = fpart_g + (size_t)b * 16 * 320 + tid;
        float v = 0.f;
#pragma unroll
        for (int s = 0; s < 16; s++) v += fp[s * 320];
        float other = __shfl_xor_sync(0xffffffffu, v, 1);
        float amp = v * v + other * other;
        int pair = tid >> 1;          // c*10 + w
        int o    = tid & 1;
        int cc   = pair / 10;
        int w    = pair - cc * 10;
        tf[w][cc + 16 * o] = amp * v; // o=0: amp*fr ; o=1: amp*fi
    }
    __syncthreads();

    // per-channel Linear(2C->2) + output-filter weighting
    {
        int w = tid >> 5;
        int q = tid & 31;
        int cc = q >> 1;
        int o  = q & 1;
        float acc = 0.f;
        const float* wn = Wnl + (cc * 2 + o) * 32;
#pragma unroll
        for (int i = 0; i < 32; i++) acc += tf[w][i] * wn[i];
        float wo = (o == 0 ? WoR : WoI)[cc * 10 + w];
        contrib[w][q] = acc * wo;
    }
    __syncthreads();

    // sum over w, write pre-BN output
    if (tid < 32) {
        float ssum = 0.f;
#pragma unroll
        for (int ww = 0; ww < 10; ww++) ssum += contrib[ww][tid];
        out_g[b * 32 + tid] = ssum;
    }
}

// ---------------- kernel 3: BatchNorm1d (R2 verbatim: 16 blocks x 512) ----------------
__global__ void __launch_bounds__(512) bn_kernel(const float* __restrict__ gamma,
                                                 const float* __restrict__ beta,
                                                 float* __restrict__ out) {
    __shared__ float sbuf[16];
    __shared__ float stat;

    int c = blockIdx.x;
    int t = threadIdx.x;
    int b = t >> 1;
    int o = t & 1;

    float v = out_g[b * 32 + c * 2 + o];

    // pass 1: mean
    float r = v;
#pragma unroll
    for (int off = 16; off; off >>= 1) r += __shfl_xor_sync(0xffffffffu, r, off);
    if ((t & 31) == 0) sbuf[t >> 5] = r;
    __syncthreads();
    if (t < 32) {
        float z = (t < 16) ? sbuf[t] : 0.f;
#pragma unroll
        for (int off = 8; off; off >>= 1) z += __shfl_xor_sync(0xffffffffu, z, off);
        if (t == 0) stat = z * (1.f / 512.f);
    }
    __syncthreads();
    float mean = stat;
    float d = v - mean;

    // pass 2: variance of centered values
    r = d * d;
#pragma unroll
    for (int off = 16; off; off >>= 1) r += __shfl_xor_sync(0xffffffffu, r, off);
    if ((t & 31) == 0) sbuf[t >> 5] = r;
    __syncthreads();
    if (t < 32) {
        float z = (t < 16) ? sbuf[t] : 0.f;
#pragma unroll
        for (int off = 8; off; off >>= 1) z += __shfl_xor_sync(0xffffffffu, z, off);
        if (t == 0) stat = rsqrtf(z * (1.f / 512.f) + 1e-5f);
    }
    __syncthreads();

    out[b * 32 + c * 2 + o] = d * stat * gamma[c] + beta[c];
}

// ---------------- launch ----------------
extern "C" void kernel_launch(void* const* d_in, const int* in_sizes, int n_in,
                              void* d_out, int out_size) {
    const float* x     = (const float*)d_in[0];
    const float* wir   = (const float*)d_in[1];
    const float* wii   = (const float*)d_in[2];
    const float* wnl   = (const float*)d_in[3];
    const float* wor   = (const float*)d_in[4];
    const float* woi   = (const float*)d_in[5];
    const float* gamma = (const float*)d_in[6];
    const float* beta  = (const float*)d_in[7];
    float* out = (float*)d_out;

    pack_kernel<<<dim3(16, 17), 256>>>(wir, wii);
    stage1_kernel<<<dim3(256, 16), 256>>>(x);
    stage23_kernel<<<256, 320>>>(wnl, wor, woi);
    bn_kernel<<<16, 512>>>(gamma, beta, out);
}